// round 2
// baseline (speedup 1.0000x reference)
#include <cuda_runtime.h>
#include <cstdint>

#define TOT      309760      // 3872 * 80
#define NCLS     80
#define FH       128
#define FW       192
#define HW       24576       // FH*FW
#define WORDS    768         // HW/32
#define NPRE     500
#define MAXI     100
#define OH       512
#define OW       768
#define CAND_CAP 2048

#define OFF_SCORES 0
#define OFF_LABELS 100
#define OFF_MASKS  200
#define MASKS_ELEMS (100LL*512LL*768LL)
#define OFF_BOXES  (200LL + MASKS_ELEMS)
#define OUT_FULL   (OFF_BOXES + 400LL)

// ----------------- device scratch (no allocation allowed) -----------------
__device__ unsigned int g_hist1[4096];
__device__ unsigned int g_hist2[4096];
__device__ unsigned int g_candCount;
__device__ unsigned int g_B1;
__device__ unsigned int g_cntAbove1;
__device__ unsigned int g_uLo;
__device__ unsigned long long g_cand[CAND_CAP];

__device__ float g_score0[NPRE];
__device__ int   g_idx0[NPRE];
__device__ unsigned int g_maskbits[NPRE * WORDS];
__device__ float g_summask[NPRE];
__device__ float g_score1[NPRE];

__device__ int   g_sorder[NPRE];
__device__ int   g_slabel[NPRE];
__device__ float g_sscore[NPRE];
__device__ float g_ssm[NPRE];

__device__ float g_dec[NPRE * NPRE];
__device__ float g_comp[NPRE];
__device__ float g_score2[NPRE];

__device__ int   g_finalg[MAXI];
__device__ float g_fscore[MAXI];
__device__ int   g_box[MAXI * 4];   // xmin, ymin, xmax, ymax

// ----------------- helpers -----------------
__device__ __forceinline__ unsigned mapu(float v) {
    unsigned b = __float_as_uint(v);
    return (b & 0x80000000u) ? ~b : (b | 0x80000000u);
}

__device__ __forceinline__ float stride_of(int g) {
    if (g < 2896) return 8.0f;     // levels 0,1
    if (g < 3472) return 16.0f;    // level 2
    return 32.0f;                  // levels 3,4
}

__device__ __forceinline__ void lin_w(int o, int S, int& i0, int& i1, float& w0, float& w1) {
    float pos = (o + 0.5f) * 0.25f - 0.5f;
    float f = floorf(pos);
    int ii = (int)f;
    float t = pos - f;
    if (ii < 0)      { ii = 0;     t = 0.0f; }
    if (ii >= S - 1) { ii = S - 1; t = 0.0f; }
    i0 = ii;
    i1 = min(ii + 1, S - 1);
    w1 = t;
    w0 = 1.0f - t;
}

// ----------------- kernels -----------------
__global__ void k_reset() {
    int t = blockIdx.x * blockDim.x + threadIdx.x;
    int stride = gridDim.x * blockDim.x;
    for (int i = t; i < 4096; i += stride) { g_hist1[i] = 0u; g_hist2[i] = 0u; }
    if (t == 0) g_candCount = 0u;
    for (int k = t; k < MAXI; k += stride) {
        g_box[k*4+0] = OW;   // xmin default IMG_W
        g_box[k*4+1] = OH;   // ymin default IMG_H
        g_box[k*4+2] = 0;    // xmax default 0
        g_box[k*4+3] = 0;    // ymax default 0
    }
}

__global__ void k_hist1(const float* __restrict__ cate) {
    __shared__ unsigned sh[4096];
    for (int i = threadIdx.x; i < 4096; i += blockDim.x) sh[i] = 0u;
    __syncthreads();
    int stride = gridDim.x * blockDim.x;
    for (int i = blockIdx.x * blockDim.x + threadIdx.x; i < TOT; i += stride) {
        float v = cate[i];
        float mv = (v > 0.1f) ? v : -1.0f;
        atomicAdd(&sh[mapu(mv) >> 20], 1u);
    }
    __syncthreads();
    for (int i = threadIdx.x; i < 4096; i += blockDim.x)
        if (sh[i]) atomicAdd(&g_hist1[i], sh[i]);
}

// suffix-scan 4096 buckets, find bucket containing rank NPRE (counting from top)
__global__ void k_find1() {
    __shared__ unsigned a[4096], b[4096];
    int t = threadIdx.x;
    for (int i = t; i < 4096; i += blockDim.x) a[i] = g_hist1[i];
    __syncthreads();
    unsigned* src = a; unsigned* dst = b;
    for (int off = 1; off < 4096; off <<= 1) {
        for (int i = t; i < 4096; i += blockDim.x)
            dst[i] = src[i] + ((i + off < 4096) ? src[i + off] : 0u);
        __syncthreads();
        unsigned* tmp = src; src = dst; dst = tmp;
    }
    for (int i = t; i < 4096; i += blockDim.x) {
        unsigned s = src[i];
        unsigned sn = (i + 1 < 4096) ? src[i + 1] : 0u;
        if (s >= NPRE && sn < NPRE) { g_B1 = (unsigned)i; g_cntAbove1 = sn; }
    }
}

__global__ void k_hist2(const float* __restrict__ cate) {
    unsigned B1 = g_B1;
    int stride = gridDim.x * blockDim.x;
    for (int i = blockIdx.x * blockDim.x + threadIdx.x; i < TOT; i += stride) {
        float v = cate[i];
        float mv = (v > 0.1f) ? v : -1.0f;
        unsigned u = mapu(mv);
        if ((u >> 20) == B1) atomicAdd(&g_hist2[(u >> 8) & 0xFFFu], 1u);
    }
}

__global__ void k_find2() {
    __shared__ unsigned a[4096], b[4096];
    int t = threadIdx.x;
    unsigned K2 = NPRE - g_cntAbove1;
    for (int i = t; i < 4096; i += blockDim.x) a[i] = g_hist2[i];
    __syncthreads();
    unsigned* src = a; unsigned* dst = b;
    for (int off = 1; off < 4096; off <<= 1) {
        for (int i = t; i < 4096; i += blockDim.x)
            dst[i] = src[i] + ((i + off < 4096) ? src[i + off] : 0u);
        __syncthreads();
        unsigned* tmp = src; src = dst; dst = tmp;
    }
    for (int i = t; i < 4096; i += blockDim.x) {
        unsigned s = src[i];
        unsigned sn = (i + 1 < 4096) ? src[i + 1] : 0u;
        if (s >= K2 && sn < K2) g_uLo = (g_B1 << 20) | ((unsigned)i << 8);
    }
}

__global__ void k_compact(const float* __restrict__ cate) {
    unsigned uLo = g_uLo;
    int stride = gridDim.x * blockDim.x;
    for (int i = blockIdx.x * blockDim.x + threadIdx.x; i < TOT; i += stride) {
        float v = cate[i];
        float mv = (v > 0.1f) ? v : -1.0f;
        unsigned u = mapu(mv);
        if (u >= uLo) {
            unsigned pos = atomicAdd(&g_candCount, 1u);
            if (pos < CAND_CAP)
                g_cand[pos] = ((unsigned long long)u << 32) | (unsigned)(~(unsigned)i);
        }
    }
}

// bitonic sort CAND_CAP candidates descending, keep top NPRE
__global__ void k_sort_cand() {
    __shared__ unsigned long long sk[CAND_CAP];
    int t = threadIdx.x;
    unsigned cnt = min(g_candCount, (unsigned)CAND_CAP);
    for (int i = t; i < CAND_CAP; i += blockDim.x)
        sk[i] = (i < (int)cnt) ? g_cand[i] : 0ull;
    __syncthreads();
    for (int k = 2; k <= CAND_CAP; k <<= 1) {
        for (int j = k >> 1; j > 0; j >>= 1) {
            for (int i = t; i < CAND_CAP; i += blockDim.x) {
                int ixj = i ^ j;
                if (ixj > i) {
                    bool up = ((i & k) == 0);
                    unsigned long long a = sk[i], b = sk[ixj];
                    bool sw = up ? (a < b) : (a > b);
                    if (sw) { sk[i] = b; sk[ixj] = a; }
                }
            }
            __syncthreads();
        }
    }
    if (t < NPRE) {
        unsigned long long key = sk[t];
        unsigned u = (unsigned)(key >> 32);
        unsigned low = (unsigned)key;
        int idx = (int)(~low);
        unsigned fb = (u & 0x80000000u) ? (u & 0x7FFFFFFFu) : ~u;
        g_score0[t] = __uint_as_float(fb);
        g_idx0[t] = idx;
    }
}

// per-candidate mask binarization + stats; bit-pack masks
__global__ void k_maskstats(const float* __restrict__ seg) {
    int i = blockIdx.x;
    int tid = threadIdx.x;
    int warp = tid >> 5, lane = tid & 31;
    int idx = g_idx0[i];
    float sc = g_score0[i];
    int g = idx / NCLS;
    const float* base = seg + (long long)g * HW;

    int cnt = 0; float ssum = 0.0f;
    for (int chunk = warp; chunk < WORDS; chunk += 8) {
        float v = base[chunk * 32 + lane];
        bool m = v > 0.5f;
        unsigned word = __ballot_sync(0xFFFFFFFFu, m);
        if (lane == 0) g_maskbits[i * WORDS + chunk] = word;
        if (m) { cnt += 1; ssum += v; }
    }
    for (int o = 16; o; o >>= 1) {
        cnt  += __shfl_down_sync(0xFFFFFFFFu, cnt, o);
        ssum += __shfl_down_sync(0xFFFFFFFFu, ssum, o);
    }
    __shared__ int scnt[8]; __shared__ float ssm[8];
    if (lane == 0) { scnt[warp] = cnt; ssm[warp] = ssum; }
    __syncthreads();
    if (tid == 0) {
        int C = 0; float S = 0.0f;
        for (int w = 0; w < 8; w++) { C += scnt[w]; S += ssm[w]; }
        float sm = (float)C;
        g_summask[i] = sm;
        bool keep = (sc > 0.1f) && (sm > stride_of(g));
        float segsc = S / fmaxf(sm, 1.0f);
        float s1 = (sc * segsc) * (keep ? 1.0f : 0.0f);
        s1 = s1 + 0.0f;   // normalize -0 -> +0
        g_score1[i] = s1;
    }
}

// stable descending sort of 500 scores (key = bits | ~pos)
__global__ void k_sort1() {
    __shared__ unsigned long long sk[512];
    int t = threadIdx.x;
    unsigned long long key = 0ull;
    if (t < NPRE) {
        unsigned b = __float_as_uint(g_score1[t]);  // >= +0
        key = ((unsigned long long)b << 32) | (unsigned)(~(unsigned)t);
    }
    sk[t] = key;
    __syncthreads();
    for (int k = 2; k <= 512; k <<= 1) {
        for (int j = k >> 1; j > 0; j >>= 1) {
            int ixj = t ^ j;
            if (ixj > t) {
                bool up = ((t & k) == 0);
                unsigned long long a = sk[t], b = sk[ixj];
                bool sw = up ? (a < b) : (a > b);
                if (sw) { sk[t] = b; sk[ixj] = a; }
            }
            __syncthreads();
        }
    }
    if (t < NPRE) {
        int pos = (int)(~(unsigned)sk[t]);
        g_sorder[t] = pos;
        g_sscore[t] = g_score1[pos];
        g_slabel[t] = g_idx0[pos] % NCLS;
        g_ssm[t]    = g_summask[pos];
    }
}

// decay_iou[i][j] for i<j via popcount on packed masks
__global__ void k_pairs() {
    int j = blockIdx.x;
    int tid = threadIdx.x;
    int warp = tid >> 5, lane = tid & 31;
    int pj = g_sorder[j];
    int lj = g_slabel[j];
    float smj = g_ssm[j];
    const unsigned* mj = g_maskbits + pj * WORDS;

    for (int i = warp; i < j; i += 8) {
        if (g_slabel[i] != lj) {
            if (lane == 0) g_dec[i * NPRE + j] = 0.0f;
            continue;
        }
        int pi = g_sorder[i];
        const unsigned* mi = g_maskbits + pi * WORDS;
        int inter = 0;
        for (int w = lane; w < WORDS; w += 32)
            inter += __popc(mi[w] & mj[w]);
        for (int o = 16; o; o >>= 1)
            inter += __shfl_down_sync(0xFFFFFFFFu, inter, o);
        if (lane == 0) {
            float finter = (float)inter;
            float uni = g_ssm[i] + smj - finter;
            g_dec[i * NPRE + j] = finter / fmaxf(uni, 1e-6f);
        }
    }
}

__global__ void k_comp() {
    int j = blockIdx.x;
    int t = threadIdx.x;
    float m = 0.0f;
    for (int i = t; i < j; i += blockDim.x) m = fmaxf(m, g_dec[i * NPRE + j]);
    __shared__ float sm[256];
    sm[t] = m;
    __syncthreads();
    for (int o = 128; o; o >>= 1) {
        if (t < o) sm[t] = fmaxf(sm[t], sm[t + o]);
        __syncthreads();
    }
    if (t == 0) g_comp[j] = sm[0];
}

__global__ void k_coef() {
    int j = blockIdx.x;
    int t = threadIdx.x;
    float mn = 3.402823466e38f;
    for (int i = t; i < NPRE; i += blockDim.x) {
        float d = (i < j) ? g_dec[i * NPRE + j] : 0.0f;
        float c = g_comp[i];
        float d2 = __fmul_rn(d, d);
        float c2 = __fmul_rn(c, c);
        float arg = -__fsub_rn(d2, c2) * 0.5f;
        mn = fminf(mn, expf(arg));
    }
    __shared__ float sm[256];
    sm[t] = mn;
    __syncthreads();
    for (int o = 128; o; o >>= 1) {
        if (t < o) sm[t] = fminf(sm[t], sm[t + o]);
        __syncthreads();
    }
    if (t == 0) {
        float s2 = g_sscore[j] * sm[0];
        s2 = (s2 >= 0.05f) ? s2 : 0.0f;
        g_score2[j] = s2;
    }
}

__global__ void k_sort2(float* __restrict__ out, int writeLabels) {
    __shared__ unsigned long long sk[512];
    int t = threadIdx.x;
    unsigned long long key = 0ull;
    if (t < NPRE) {
        unsigned b = __float_as_uint(g_score2[t]);  // >= +0
        key = ((unsigned long long)b << 32) | (unsigned)(~(unsigned)t);
    }
    sk[t] = key;
    __syncthreads();
    for (int k = 2; k <= 512; k <<= 1) {
        for (int j = k >> 1; j > 0; j >>= 1) {
            int ixj = t ^ j;
            if (ixj > t) {
                bool up = ((t & k) == 0);
                unsigned long long a = sk[t], b = sk[ixj];
                bool sw = up ? (a < b) : (a > b);
                if (sw) { sk[t] = b; sk[ixj] = a; }
            }
            __syncthreads();
        }
    }
    if (t < MAXI) {
        int pos = (int)(~(unsigned)sk[t]);
        float s = g_score2[pos];
        g_fscore[t] = s;
        out[OFF_SCORES + t] = s;
        if (writeLabels) out[OFF_LABELS + t] = (float)g_slabel[pos];
        g_finalg[t] = g_idx0[g_sorder[pos]] / NCLS;
    }
}

// bilinear 4x upsample (W pass then H pass, fma like XLA), threshold, bbox reduce
__global__ void k_upsample(const float* __restrict__ seg, float* __restrict__ out) {
    int y = blockIdx.x;       // 0..511
    int k = blockIdx.y;       // 0..99
    int tid = threadIdx.x;
    int g = g_finalg[k];
    const float* base = seg + (long long)g * HW;

    int y0, y1; float wy0, wy1;
    lin_w(y, FH, y0, y1, wy0, wy1);
    const float* r0 = base + y0 * FW;
    const float* r1 = base + y1 * FW;

    float* orow = out + OFF_MASKS + (long long)k * (OH * OW) + (long long)y * OW;

    int lminx = 0x7FFFFFFF, lmaxx = -1;
    for (int p = 0; p < 3; p++) {
        int x = tid + 256 * p;
        int x0, x1; float wx0, wx1;
        lin_w(x, FW, x0, x1, wx0, wx1);
        float t0 = fmaf(wx1, r0[x1], wx0 * r0[x0]);
        float t1 = fmaf(wx1, r1[x1], wx0 * r1[x0]);
        float v  = fmaf(wy1, t1, wy0 * t0);
        bool m = v > 0.5f;
        orow[x] = m ? 1.0f : 0.0f;
        if (m) { lminx = min(lminx, x); lmaxx = max(lmaxx, x); }
    }
    __shared__ int smin[256], smax[256];
    smin[tid] = lminx; smax[tid] = lmaxx;
    __syncthreads();
    for (int o = 128; o; o >>= 1) {
        if (tid < o) {
            smin[tid] = min(smin[tid], smin[tid + o]);
            smax[tid] = max(smax[tid], smax[tid + o]);
        }
        __syncthreads();
    }
    if (tid == 0 && smax[0] >= 0) {
        atomicMin(&g_box[k*4+0], smin[0]);
        atomicMin(&g_box[k*4+1], y);
        atomicMax(&g_box[k*4+2], smax[0]);
        atomicMax(&g_box[k*4+3], y);
    }
}

__global__ void k_boxes(float* __restrict__ out) {
    int k = threadIdx.x;
    if (k < MAXI) {
        float f = (g_fscore[k] > 0.0f) ? 1.0f : 0.0f;
        out[OFF_BOXES + k*4 + 0] = (float)g_box[k*4+0] * f;
        out[OFF_BOXES + k*4 + 1] = (float)g_box[k*4+1] * f;
        out[OFF_BOXES + k*4 + 2] = (float)g_box[k*4+2] * f;
        out[OFF_BOXES + k*4 + 3] = (float)g_box[k*4+3] * f;
    }
}

// ----------------- launch -----------------
extern "C" void kernel_launch(void* const* d_in, const int* in_sizes, int n_in,
                              void* d_out, int out_size) {
    const float* cate = (const float*)d_in[0];
    const float* seg  = (const float*)d_in[1];
    float* out = (float*)d_out;
    int full = (out_size >= (int)OUT_FULL) ? 1 : 0;

    k_reset<<<32, 256>>>();
    k_hist1<<<512, 256>>>(cate);
    k_find1<<<1, 1024>>>();
    k_hist2<<<512, 256>>>(cate);
    k_find2<<<1, 1024>>>();
    k_compact<<<512, 256>>>(cate);
    k_sort_cand<<<1, 1024>>>();
    k_maskstats<<<NPRE, 256>>>(seg);
    k_sort1<<<1, 512>>>();
    k_pairs<<<NPRE, 256>>>();
    k_comp<<<NPRE, 256>>>();
    k_coef<<<NPRE, 256>>>();
    k_sort2<<<1, 512>>>(out, full);
    if (full) {
        dim3 grid(OH, MAXI);
        k_upsample<<<grid, 256>>>(seg, out);
        k_boxes<<<1, 128>>>(out);
    }
}